// round 2
// baseline (speedup 1.0000x reference)
#include <cuda_runtime.h>
#include <cuda_bf16.h>
#include <float.h>

// ROI pooling: crop_and_resize (bilinear, 14x14) + 2x2 max pool -> (N,7,7,512)
// feature_map: (1, 50, 75, 512) fp32 NHWC ; rois: (N,4) [x1,y1,x2,y2] ; img_size: (2,) int32
//
// Parallelization: grid = (N, 7 pooled rows), block = 128 threads.
// Each thread owns one float4 (4 channels); 128 threads cover all 512 channels,
// so every corner gather is one fully-coalesced 2KB transaction per block.

#define FH 50
#define FW 75
#define FC 512
#define NPOOL 7
#define CROPDIM 14

__device__ __forceinline__ float flerp(float a, float b, float t) {
    return fmaf(t, b - a, a);
}

__global__ __launch_bounds__(128) void roi_pool_kernel(
    const float* __restrict__ fmap,
    const float* __restrict__ rois,
    const int*   __restrict__ img_size,
    float*       __restrict__ out)
{
    const int n  = blockIdx.x;   // roi index
    const int py = blockIdx.y;   // pooled row 0..6
    const int c4 = threadIdx.x;  // float4 channel chunk 0..127

    // ---- uniform per-block scalar setup ----
    const float ih = (float)img_size[0] - 1.0f;   // 799
    const float iw = (float)img_size[1] - 1.0f;   // 1199
    const float4 r = reinterpret_cast<const float4*>(rois)[n]; // x1,y1,x2,y2
    const float bx1 = r.x / iw;
    const float by1 = r.y / ih;
    const float bx2 = r.z / iw;
    const float by2 = r.w / ih;

    const float fh = (float)(FH - 1);   // 49
    const float fw = (float)(FW - 1);   // 74
    const float sy = (by2 - by1) * fh * (1.0f / (CROPDIM - 1));
    const float sx = (bx2 - bx1) * fw * (1.0f / (CROPDIM - 1));
    const float yb = by1 * fh;
    const float xb = bx1 * fw;

    // two crop rows feeding this pooled row
    int   y0i[2], y1i[2];
    float wy[2];
    bool  yv[2];
#pragma unroll
    for (int j = 0; j < 2; j++) {
        const float ys = fmaf((float)(2 * py + j), sy, yb);
        yv[j] = (ys >= 0.0f) && (ys <= fh);
        const float y0 = floorf(ys);
        wy[j] = ys - y0;
        int yi = (int)y0;
        yi = min(max(yi, 0), FH - 1);
        y0i[j] = yi;
        y1i[j] = min(yi + 1, FH - 1);
    }

    const float4* __restrict__ f4 = reinterpret_cast<const float4*>(fmap);
    float4* __restrict__ o4 = reinterpret_cast<float4*>(out);

    const int C4 = FC / 4; // 128

    for (int px = 0; px < NPOOL; px++) {
        float4 m = make_float4(-FLT_MAX, -FLT_MAX, -FLT_MAX, -FLT_MAX);
#pragma unroll
        for (int i = 0; i < 2; i++) {
            const float xs = fmaf((float)(2 * px + i), sx, xb);
            const bool xv = (xs >= 0.0f) && (xs <= fw);
            const float x0 = floorf(xs);
            const float wx = xs - x0;
            int xi = (int)x0;
            xi = min(max(xi, 0), FW - 1);
            const int xj = min(xi + 1, FW - 1);
#pragma unroll
            for (int j = 0; j < 2; j++) {
                const long rowA = (long)(y0i[j] * FW);
                const long rowB = (long)(y1i[j] * FW);
                const float4 tl = __ldg(&f4[(rowA + xi) * C4 + c4]);
                const float4 tr = __ldg(&f4[(rowA + xj) * C4 + c4]);
                const float4 bl = __ldg(&f4[(rowB + xi) * C4 + c4]);
                const float4 br = __ldg(&f4[(rowB + xj) * C4 + c4]);
                const float w = wy[j];
                float4 v;
                v.x = flerp(flerp(tl.x, tr.x, wx), flerp(bl.x, br.x, wx), w);
                v.y = flerp(flerp(tl.y, tr.y, wx), flerp(bl.y, br.y, wx), w);
                v.z = flerp(flerp(tl.z, tr.z, wx), flerp(bl.z, br.z, wx), w);
                v.w = flerp(flerp(tl.w, tr.w, wx), flerp(bl.w, br.w, wx), w);
                const bool valid = xv && yv[j];
                if (!valid) v = make_float4(0.0f, 0.0f, 0.0f, 0.0f);
                m.x = fmaxf(m.x, v.x);
                m.y = fmaxf(m.y, v.y);
                m.z = fmaxf(m.z, v.z);
                m.w = fmaxf(m.w, v.w);
            }
        }
        o4[((long)(n * (NPOOL * NPOOL) + py * NPOOL + px)) * C4 + c4] = m;
    }
}

extern "C" void kernel_launch(void* const* d_in, const int* in_sizes, int n_in,
                              void* d_out, int out_size) {
    const float* fmap     = (const float*)d_in[0];
    const float* rois     = (const float*)d_in[1];
    const int*   img_size = (const int*)d_in[2];
    float* out = (float*)d_out;

    const int N = in_sizes[1] / 4;   // number of rois
    dim3 grid(N, NPOOL);
    dim3 block(128);
    roi_pool_kernel<<<grid, block>>>(fmap, rois, img_size, out);
}

// round 3
// speedup vs baseline: 1.0103x; 1.0103x over previous
#include <cuda_runtime.h>
#include <cuda_bf16.h>
#include <float.h>

// ROI pooling: crop_and_resize (bilinear, 14x14) + 2x2 max pool -> (N,7,7,512)
// feature_map: (1, 50, 75, 512) fp32 NHWC ; rois: (N,4) [x1,y1,x2,y2] ; img_size: (2,) int32
//
// grid = N rois, block = 128 threads (one float4 of channels per thread).
// py loop inside block amortizes scalar setup; weight-product bilinear
// (4 FFMA/comp) with the validity mask folded into the scalar weights.

#define FH 50
#define FW 75
#define FC 512
#define NPOOL 7
#define CROPDIM 14
#define C4 (FC / 4)

__global__ __launch_bounds__(128) void roi_pool_kernel(
    const float* __restrict__ fmap,
    const float* __restrict__ rois,
    const int*   __restrict__ img_size,
    float*       __restrict__ out)
{
    const int n  = blockIdx.x;   // roi index
    const int c4 = threadIdx.x;  // float4 channel chunk 0..127

    // ---- uniform per-block scalar setup ----
    const float ih = (float)img_size[0] - 1.0f;   // 799
    const float iw = (float)img_size[1] - 1.0f;   // 1199
    const float4 r = reinterpret_cast<const float4*>(rois)[n]; // x1,y1,x2,y2
    const float bx1 = r.x / iw;
    const float by1 = r.y / ih;
    const float bx2 = r.z / iw;
    const float by2 = r.w / ih;

    const float fh = (float)(FH - 1);   // 49
    const float fw = (float)(FW - 1);   // 74
    const float sy = (by2 - by1) * fh * (1.0f / (CROPDIM - 1));
    const float sx = (bx2 - bx1) * fw * (1.0f / (CROPDIM - 1));
    const float yb = by1 * fh;
    const float xb = bx1 * fw;

    // ---- precompute all 14 crop-column params (uniform scalars) ----
    int   xi_a[CROPDIM], xj_a[CROPDIM];
    float wxg_a[CROPDIM], omwxg_a[CROPDIM];   // gated by x-validity
#pragma unroll
    for (int k = 0; k < CROPDIM; k++) {
        const float xs = fmaf((float)k, sx, xb);
        const float gx = ((xs >= 0.0f) && (xs <= fw)) ? 1.0f : 0.0f;
        const float x0 = floorf(xs);
        const float wx = xs - x0;
        int xi = (int)x0;
        xi = min(max(xi, 0), FW - 1);
        xi_a[k] = xi;
        xj_a[k] = min(xi + 1, FW - 1);
        wxg_a[k]   = wx * gx;
        omwxg_a[k] = (1.0f - wx) * gx;
    }

    const float4* __restrict__ fb = reinterpret_cast<const float4*>(fmap) + c4;
    float4* __restrict__ ob = reinterpret_cast<float4*>(out) + (long)n * (NPOOL * NPOOL) * C4 + c4;

    for (int py = 0; py < NPOOL; py++) {
        // two crop rows feeding this pooled row (uniform scalars)
        int   rowT[2], rowB[2];
        float wyg[2], omwyg[2];
#pragma unroll
        for (int j = 0; j < 2; j++) {
            const float ys = fmaf((float)(2 * py + j), sy, yb);
            const float gy = ((ys >= 0.0f) && (ys <= fh)) ? 1.0f : 0.0f;
            const float y0 = floorf(ys);
            const float wy = ys - y0;
            int yi = (int)y0;
            yi = min(max(yi, 0), FH - 1);
            rowT[j] = yi * FW * C4;
            rowB[j] = min(yi + 1, FH - 1) * FW * C4;
            wyg[j]   = wy * gy;
            omwyg[j] = (1.0f - wy) * gy;
        }

#pragma unroll
        for (int px = 0; px < NPOOL; px++) {
            float4 vv[2][2];
#pragma unroll
            for (int i = 0; i < 2; i++) {
                const int k = 2 * px + i;
                const int cA = xi_a[k] * C4;
                const int cB = xj_a[k] * C4;
                const float wxg   = wxg_a[k];
                const float omwxg = omwxg_a[k];
#pragma unroll
                for (int j = 0; j < 2; j++) {
                    const float4 tl = __ldg(fb + rowT[j] + cA);
                    const float4 tr = __ldg(fb + rowT[j] + cB);
                    const float4 bl = __ldg(fb + rowB[j] + cA);
                    const float4 br = __ldg(fb + rowB[j] + cB);
                    const float w00 = omwyg[j] * omwxg;
                    const float w01 = omwyg[j] * wxg;
                    const float w10 = wyg[j]   * omwxg;
                    const float w11 = wyg[j]   * wxg;
                    float4 v;
                    v.x = fmaf(br.x, w11, fmaf(bl.x, w10, fmaf(tr.x, w01, tl.x * w00)));
                    v.y = fmaf(br.y, w11, fmaf(bl.y, w10, fmaf(tr.y, w01, tl.y * w00)));
                    v.z = fmaf(br.z, w11, fmaf(bl.z, w10, fmaf(tr.z, w01, tl.z * w00)));
                    v.w = fmaf(br.w, w11, fmaf(bl.w, w10, fmaf(tr.w, w01, tl.w * w00)));
                    vv[i][j] = v;
                }
            }
            float4 m;
            m.x = fmaxf(fmaxf(vv[0][0].x, vv[0][1].x), fmaxf(vv[1][0].x, vv[1][1].x));
            m.y = fmaxf(fmaxf(vv[0][0].y, vv[0][1].y), fmaxf(vv[1][0].y, vv[1][1].y));
            m.z = fmaxf(fmaxf(vv[0][0].z, vv[0][1].z), fmaxf(vv[1][0].z, vv[1][1].z));
            m.w = fmaxf(fmaxf(vv[0][0].w, vv[0][1].w), fmaxf(vv[1][0].w, vv[1][1].w));
            ob[(py * NPOOL + px) * C4] = m;
        }
    }
}

extern "C" void kernel_launch(void* const* d_in, const int* in_sizes, int n_in,
                              void* d_out, int out_size) {
    const float* fmap     = (const float*)d_in[0];
    const float* rois     = (const float*)d_in[1];
    const int*   img_size = (const int*)d_in[2];
    float* out = (float*)d_out;

    const int N = in_sizes[1] / 4;   // number of rois
    roi_pool_kernel<<<N, 128>>>(fmap, rois, img_size, out);
}

// round 4
// speedup vs baseline: 1.1510x; 1.1393x over previous
#include <cuda_runtime.h>
#include <cuda_bf16.h>
#include <float.h>

// ROI pooling: crop_and_resize (bilinear, 14x14) + 2x2 max pool -> (N,7,7,512)
// feature_map: (1, 50, 75, 512) fp32 NHWC ; rois: (N,4) [x1,y1,x2,y2] ; img_size: (2,) int32
//
// grid = (N, 7 pooled rows), block = 128 threads (one float4 of channels per thread).
// Weight-product bilinear (4 FFMA/comp), validity mask folded into scalar weights,
// x-column params computed inline per px to keep register count low / occupancy high.

#define FH 50
#define FW 75
#define FC 512
#define NPOOL 7
#define CROPDIM 14
#define C4 (FC / 4)

__global__ __launch_bounds__(128) void roi_pool_kernel(
    const float* __restrict__ fmap,
    const float* __restrict__ rois,
    const int*   __restrict__ img_size,
    float*       __restrict__ out)
{
    const int n  = blockIdx.x;   // roi index
    const int py = blockIdx.y;   // pooled row 0..6
    const int c4 = threadIdx.x;  // float4 channel chunk 0..127

    // ---- uniform per-block scalar setup ----
    const float ih = (float)img_size[0] - 1.0f;   // 799
    const float iw = (float)img_size[1] - 1.0f;   // 1199
    const float4 r = reinterpret_cast<const float4*>(rois)[n]; // x1,y1,x2,y2
    const float bx1 = r.x / iw;
    const float by1 = r.y / ih;
    const float bx2 = r.z / iw;
    const float by2 = r.w / ih;

    const float fh = (float)(FH - 1);   // 49
    const float fw = (float)(FW - 1);   // 74
    const float sy = (by2 - by1) * fh * (1.0f / (CROPDIM - 1));
    const float sx = (bx2 - bx1) * fw * (1.0f / (CROPDIM - 1));
    const float yb = by1 * fh;
    const float xb = bx1 * fw;

    // two crop rows feeding this pooled row (uniform scalars)
    int   rowT[2], rowB[2];
    float wyg[2], omwyg[2];
#pragma unroll
    for (int j = 0; j < 2; j++) {
        const float ys = fmaf((float)(2 * py + j), sy, yb);
        const float gy = ((ys >= 0.0f) && (ys <= fh)) ? 1.0f : 0.0f;
        const float y0 = floorf(ys);
        const float wy = ys - y0;
        int yi = (int)y0;
        yi = min(max(yi, 0), FH - 1);
        rowT[j] = yi * FW * C4;
        rowB[j] = min(yi + 1, FH - 1) * FW * C4;
        wyg[j]   = wy * gy;
        omwyg[j] = (1.0f - wy) * gy;
    }

    const float4* __restrict__ fb = reinterpret_cast<const float4*>(fmap) + c4;
    float4* __restrict__ ob = reinterpret_cast<float4*>(out)
        + ((long)n * (NPOOL * NPOOL) + py * NPOOL) * C4 + c4;

#pragma unroll
    for (int px = 0; px < NPOOL; px++) {
        float4 vv[2][2];
#pragma unroll
        for (int i = 0; i < 2; i++) {
            const float xs = fmaf((float)(2 * px + i), sx, xb);
            const float gx = ((xs >= 0.0f) && (xs <= fw)) ? 1.0f : 0.0f;
            const float x0 = floorf(xs);
            const float wx = xs - x0;
            int xi = (int)x0;
            xi = min(max(xi, 0), FW - 1);
            const int cA = xi * C4;
            const int cB = min(xi + 1, FW - 1) * C4;
            const float wxg   = wx * gx;
            const float omwxg = (1.0f - wx) * gx;
#pragma unroll
            for (int j = 0; j < 2; j++) {
                const float4 tl = __ldg(fb + rowT[j] + cA);
                const float4 tr = __ldg(fb + rowT[j] + cB);
                const float4 bl = __ldg(fb + rowB[j] + cA);
                const float4 br = __ldg(fb + rowB[j] + cB);
                const float w00 = omwyg[j] * omwxg;
                const float w01 = omwyg[j] * wxg;
                const float w10 = wyg[j]   * omwxg;
                const float w11 = wyg[j]   * wxg;
                float4 v;
                v.x = fmaf(br.x, w11, fmaf(bl.x, w10, fmaf(tr.x, w01, tl.x * w00)));
                v.y = fmaf(br.y, w11, fmaf(bl.y, w10, fmaf(tr.y, w01, tl.y * w00)));
                v.z = fmaf(br.z, w11, fmaf(bl.z, w10, fmaf(tr.z, w01, tl.z * w00)));
                v.w = fmaf(br.w, w11, fmaf(bl.w, w10, fmaf(tr.w, w01, tl.w * w00)));
                vv[i][j] = v;
            }
        }
        float4 m;
        m.x = fmaxf(fmaxf(vv[0][0].x, vv[0][1].x), fmaxf(vv[1][0].x, vv[1][1].x));
        m.y = fmaxf(fmaxf(vv[0][0].y, vv[0][1].y), fmaxf(vv[1][0].y, vv[1][1].y));
        m.z = fmaxf(fmaxf(vv[0][0].z, vv[0][1].z), fmaxf(vv[1][0].z, vv[1][1].z));
        m.w = fmaxf(fmaxf(vv[0][0].w, vv[0][1].w), fmaxf(vv[1][0].w, vv[1][1].w));
        ob[px * C4] = m;
    }
}

extern "C" void kernel_launch(void* const* d_in, const int* in_sizes, int n_in,
                              void* d_out, int out_size) {
    const float* fmap     = (const float*)d_in[0];
    const float* rois     = (const float*)d_in[1];
    const int*   img_size = (const int*)d_in[2];
    float* out = (float*)d_out;

    const int N = in_sizes[1] / 4;   // number of rois
    dim3 grid(N, NPOOL);
    roi_pool_kernel<<<grid, 128>>>(fmap, rois, img_size, out);
}

// round 5
// speedup vs baseline: 1.2529x; 1.0885x over previous
#include <cuda_runtime.h>
#include <cuda_bf16.h>
#include <float.h>

// ROI pooling: crop_and_resize (bilinear, 14x14) + 2x2 max pool -> (N,7,7,512)
// feature_map: (1, 50, 75, 512) fp32 NHWC ; rois: (N,4) [x1,y1,x2,y2] ; img_size: (2,) int32
//
// grid = (N, 7 pooled rows), block = 128 threads (one float4 of channels per thread).
// Horizontal-lerp-per-feature-row then vertical lerp; when the two crop rows of a
// pooled row share a feature row (rowB[0]==rowT[1], ~70% of blocks, uniform scalar
// condition) the shared row's loads AND its horizontal lerp are reused -> 6 loads
// instead of 8 per (px,i). Validity mask folded into scalar weights.

#define FH 50
#define FW 75
#define FC 512
#define NPOOL 7
#define CROPDIM 14
#define C4 (FC / 4)

__global__ __launch_bounds__(128) void roi_pool_kernel(
    const float* __restrict__ fmap,
    const float* __restrict__ rois,
    const int*   __restrict__ img_size,
    float*       __restrict__ out)
{
    const int n  = blockIdx.x;   // roi index
    const int py = blockIdx.y;   // pooled row 0..6
    const int c4 = threadIdx.x;  // float4 channel chunk 0..127

    // ---- uniform per-block scalar setup ----
    const float ih = (float)img_size[0] - 1.0f;   // 799
    const float iw = (float)img_size[1] - 1.0f;   // 1199
    const float4 r = reinterpret_cast<const float4*>(rois)[n]; // x1,y1,x2,y2
    const float bx1 = r.x / iw;
    const float by1 = r.y / ih;
    const float bx2 = r.z / iw;
    const float by2 = r.w / ih;

    const float fh = (float)(FH - 1);   // 49
    const float fw = (float)(FW - 1);   // 74
    const float sy = (by2 - by1) * fh * (1.0f / (CROPDIM - 1));
    const float sx = (bx2 - bx1) * fw * (1.0f / (CROPDIM - 1));
    const float yb = by1 * fh;
    const float xb = bx1 * fw;

    // two crop rows feeding this pooled row (uniform scalars)
    int   row0, row1, row2, row3;     // feature-row byte offsets (in float4 units)
    float wyg0, omwyg0, wyg1, omwyg1;
    {
        const float ys0 = fmaf((float)(2 * py), sy, yb);
        const float gy0 = ((ys0 >= 0.0f) && (ys0 <= fh)) ? 1.0f : 0.0f;
        const float fl0 = floorf(ys0);
        const float wy0 = ys0 - fl0;
        int yi0 = min(max((int)fl0, 0), FH - 1);
        row0 = yi0 * (FW * C4);
        row1 = min(yi0 + 1, FH - 1) * (FW * C4);
        wyg0 = wy0 * gy0;  omwyg0 = (1.0f - wy0) * gy0;

        const float ys1 = fmaf((float)(2 * py + 1), sy, yb);
        const float gy1 = ((ys1 >= 0.0f) && (ys1 <= fh)) ? 1.0f : 0.0f;
        const float fl1 = floorf(ys1);
        const float wy1 = ys1 - fl1;
        int yi1 = min(max((int)fl1, 0), FH - 1);
        row2 = yi1 * (FW * C4);
        row3 = min(yi1 + 1, FH - 1) * (FW * C4);
        wyg1 = wy1 * gy1;  omwyg1 = (1.0f - wy1) * gy1;
    }
    const bool shared_row = (row2 == row1);   // uniform across the block

    const float4* __restrict__ fb = reinterpret_cast<const float4*>(fmap) + c4;
    float4* __restrict__ ob = reinterpret_cast<float4*>(out)
        + ((long)n * (NPOOL * NPOOL) + py * NPOOL) * C4 + c4;

#pragma unroll
    for (int px = 0; px < NPOOL; px++) {
        float4 m = make_float4(-FLT_MAX, -FLT_MAX, -FLT_MAX, -FLT_MAX);
#pragma unroll
        for (int i = 0; i < 2; i++) {
            const float xs = fmaf((float)(2 * px + i), sx, xb);
            const float gx = ((xs >= 0.0f) && (xs <= fw)) ? 1.0f : 0.0f;
            const float x0 = floorf(xs);
            const float wx = xs - x0;
            int xi = min(max((int)x0, 0), FW - 1);
            const int cA = xi * C4;
            const int cB = min(xi + 1, FW - 1) * C4;
            const float wxg   = wx * gx;
            const float omwxg = (1.0f - wx) * gx;

            // horizontal lerp per distinct feature row
            const float4 a0 = __ldg(fb + row0 + cA);
            const float4 b0 = __ldg(fb + row0 + cB);
            const float4 a1 = __ldg(fb + row1 + cA);
            const float4 b1 = __ldg(fb + row1 + cB);
            const float4 a3 = __ldg(fb + row3 + cA);
            const float4 b3 = __ldg(fb + row3 + cB);

            float4 h0, h1, h3;
            h0.x = fmaf(b0.x, wxg, a0.x * omwxg);
            h0.y = fmaf(b0.y, wxg, a0.y * omwxg);
            h0.z = fmaf(b0.z, wxg, a0.z * omwxg);
            h0.w = fmaf(b0.w, wxg, a0.w * omwxg);
            h1.x = fmaf(b1.x, wxg, a1.x * omwxg);
            h1.y = fmaf(b1.y, wxg, a1.y * omwxg);
            h1.z = fmaf(b1.z, wxg, a1.z * omwxg);
            h1.w = fmaf(b1.w, wxg, a1.w * omwxg);
            h3.x = fmaf(b3.x, wxg, a3.x * omwxg);
            h3.y = fmaf(b3.y, wxg, a3.y * omwxg);
            h3.z = fmaf(b3.z, wxg, a3.z * omwxg);
            h3.w = fmaf(b3.w, wxg, a3.w * omwxg);

            float4 h2;
            if (shared_row) {
                h2 = h1;
            } else {
                const float4 a2 = __ldg(fb + row2 + cA);
                const float4 b2 = __ldg(fb + row2 + cB);
                h2.x = fmaf(b2.x, wxg, a2.x * omwxg);
                h2.y = fmaf(b2.y, wxg, a2.y * omwxg);
                h2.z = fmaf(b2.z, wxg, a2.z * omwxg);
                h2.w = fmaf(b2.w, wxg, a2.w * omwxg);
            }

            // vertical lerp for the two crop rows, then max-accumulate
            float4 v0, v1;
            v0.x = fmaf(h1.x, wyg0, h0.x * omwyg0);
            v0.y = fmaf(h1.y, wyg0, h0.y * omwyg0);
            v0.z = fmaf(h1.z, wyg0, h0.z * omwyg0);
            v0.w = fmaf(h1.w, wyg0, h0.w * omwyg0);
            v1.x = fmaf(h3.x, wyg1, h2.x * omwyg1);
            v1.y = fmaf(h3.y, wyg1, h2.y * omwyg1);
            v1.z = fmaf(h3.z, wyg1, h2.z * omwyg1);
            v1.w = fmaf(h3.w, wyg1, h2.w * omwyg1);

            m.x = fmaxf(m.x, fmaxf(v0.x, v1.x));
            m.y = fmaxf(m.y, fmaxf(v0.y, v1.y));
            m.z = fmaxf(m.z, fmaxf(v0.z, v1.z));
            m.w = fmaxf(m.w, fmaxf(v0.w, v1.w));
        }
        ob[px * C4] = m;
    }
}

extern "C" void kernel_launch(void* const* d_in, const int* in_sizes, int n_in,
                              void* d_out, int out_size) {
    const float* fmap     = (const float*)d_in[0];
    const float* rois     = (const float*)d_in[1];
    const int*   img_size = (const int*)d_in[2];
    float* out = (float*)d_out;

    const int N = in_sizes[1] / 4;   // number of rois
    dim3 grid(N, NPOOL);
    roi_pool_kernel<<<grid, 128>>>(fmap, rois, img_size, out);
}